// round 2
// baseline (speedup 1.0000x reference)
#include <cuda_runtime.h>
#include <cstdint>
#include <cstddef>

typedef unsigned long long ull;

// ---------------- output layout (float32 concat of reference tuple) -------
#define OFF_PRED 0
#define OFF_CAPS 4960000
#define OFF_DLEN 4960512
#define OFF_ALPH 4960528
#define OFF_SORT 5057744

// ---------------- device scratch (static globals: no allocs) --------------
__device__ int   g_sort[16], g_dlen[16], g_caps[512];
__device__ float g_mean[16 * 1024];
__device__ float g_att1[3136 * 1024];     // 12.8 MB
__device__ float g_h[16 * 512], g_c[16 * 512];
__device__ float g_hT[512 * 16];          // h_new transposed [d][b]
__device__ float g_xT[2048 * 16];         // X transposed [k][b]: emb|awe|h
__device__ float g_att2[16 * 1024], g_gate[16 * 1024];
__device__ float g_att[3136];
__device__ float g_gates[16 * 2048];

// ---------------- helpers ----------------
__device__ __forceinline__ ull pk(float x, float y) {
    ull u; asm("mov.b64 %0,{%1,%2};" : "=l"(u) : "f"(x), "f"(y)); return u;
}
__device__ __forceinline__ float2 upk(ull u) {
    float2 v; asm("mov.b64 {%0,%1},%2;" : "=f"(v.x), "=f"(v.y) : "l"(u)); return v;
}
__device__ __forceinline__ ull f2(ull a, ull b, ull c) {
    ull d; asm("fma.rn.f32x2 %0,%1,%2,%3;" : "=l"(d) : "l"(a), "l"(b), "l"(c)); return d;
}
__device__ __forceinline__ float sigmf(float x) { return 1.f / (1.f + expf(-x)); }

// ================= setup 1: stable sort + caps/dlen/sort_ind out ==========
__global__ void ksetup1(const int* __restrict__ caps_in,
                        const int* __restrict__ clen,
                        float* __restrict__ out) {
    int tid = threadIdx.x;
    if (tid == 0) {
        int len[16];
        #pragma unroll
        for (int i = 0; i < 16; i++) len[i] = clen[i];
        for (int i = 0; i < 16; i++) {
            int rank = 0;
            for (int j = 0; j < 16; j++)
                rank += (len[j] > len[i]) || (len[j] == len[i] && j < i);
            g_sort[rank] = i;
            g_dlen[rank] = len[i] - 1;
            out[OFF_SORT + rank] = (float)i;
            out[OFF_DLEN + rank] = (float)(len[i] - 1);
        }
    }
    __syncthreads();
    for (int j = tid; j < 512; j += 256) {
        int b = j >> 5, l = j & 31;
        int v = caps_in[g_sort[b] * 32 + l];
        g_caps[j] = v;
        out[OFF_CAPS + j] = (float)v;
    }
}

// ================= setup 2: mean over P of sorted encoder ==================
__global__ void ksetup2(const float* __restrict__ enc) {
    int j = blockIdx.x * 256 + threadIdx.x;   // 16384 = 16 b x 1024 e
    int b = j >> 10, e = j & 1023;
    const float* p0 = enc + ((size_t)g_sort[b] * 196) * 1024 + e;
    float s = 0.f;
    #pragma unroll 4
    for (int p = 0; p < 196; p++) s += p0[(size_t)p * 1024];
    g_mean[j] = s * (1.0f / 196.0f);
}

// ================= setup 3: h0, c0 (also fill xT h-rows) ===================
__global__ void ksetup3(const float* __restrict__ ihW, const float* __restrict__ ihB,
                        const float* __restrict__ icW, const float* __restrict__ icB) {
    int j = blockIdx.x * 256 + threadIdx.x;   // 16384 = 2 x 16 b x 512 d
    int which = j >> 13;
    int jj = j & 8191;
    int b = jj >> 9, d = jj & 511;
    const float* W = which ? icW : ihW;
    const float* mrow = g_mean + b * 1024;
    float acc = 0.f;
    #pragma unroll 4
    for (int k = 0; k < 1024; k++) acc += mrow[k] * W[k * 512 + d];
    float val = acc + (which ? icB[d] : ihB[d]);
    if (which) g_c[b * 512 + d] = val;
    else { g_h[b * 512 + d] = val; g_xT[(1536 + d) * 16 + b] = val; }
}

// ================= att1 GEMM: (3136x1024) = enc_sorted @ encW + b =========
// 128x128 tile, 256 threads, 8x8 micro, f32x2 accumulation
__global__ void __launch_bounds__(256, 1)
katt1(const float* __restrict__ enc, const float* __restrict__ W,
      const float* __restrict__ bias) {
    __shared__ float As[32][132];   // transposed A: As[k][m]
    __shared__ float Bs[32][128];
    int tid = threadIdx.x;
    int bm = blockIdx.y, bn = blockIdx.x;

    // A load mapping: kq in [0,8) float4-chunks of k, ml row
    int kq = tid & 7, ml = tid >> 3;
    const float* arow[4];
    #pragma unroll
    for (int ps = 0; ps < 4; ps++) {
        int m = bm * 128 + ml + ps * 32;
        int mc = m < 3135 ? m : 3135;
        int b = mc / 196, p = mc - b * 196;
        arow[ps] = enc + ((size_t)g_sort[b] * 196 + p) * 1024 + kq * 4;
    }
    // B load mapping
    int nb = tid & 31, kb = tid >> 5;
    const float* bptr = W + (size_t)kb * 1024 + bn * 128 + nb * 4;

    ull acc[8][4];
    #pragma unroll
    for (int i = 0; i < 8; i++)
        #pragma unroll
        for (int j = 0; j < 4; j++) acc[i][j] = 0ull;

    int tx = tid & 15, ty = tid >> 4;

    for (int kt = 0; kt < 1024; kt += 32) {
        #pragma unroll
        for (int ps = 0; ps < 4; ps++) {
            float4 av = *(const float4*)(arow[ps] + kt);
            int mm = ml + ps * 32;
            As[kq * 4 + 0][mm] = av.x;
            As[kq * 4 + 1][mm] = av.y;
            As[kq * 4 + 2][mm] = av.z;
            As[kq * 4 + 3][mm] = av.w;
        }
        #pragma unroll
        for (int ps = 0; ps < 4; ps++) {
            float4 bv = *(const float4*)(bptr + (size_t)(kt + ps * 8) * 1024);
            *(float4*)&Bs[kb + ps * 8][nb * 4] = bv;
        }
        __syncthreads();
        #pragma unroll 8
        for (int kk = 0; kk < 32; kk++) {
            float4 a0 = *(const float4*)&As[kk][ty * 8];
            float4 a1 = *(const float4*)&As[kk][ty * 8 + 4];
            ulonglong2 b0 = *(const ulonglong2*)&Bs[kk][tx * 8];
            ulonglong2 b1 = *(const ulonglong2*)&Bs[kk][tx * 8 + 4];
            float a[8] = {a0.x, a0.y, a0.z, a0.w, a1.x, a1.y, a1.z, a1.w};
            #pragma unroll
            for (int i = 0; i < 8; i++) {
                ull ap = pk(a[i], a[i]);
                acc[i][0] = f2(ap, b0.x, acc[i][0]);
                acc[i][1] = f2(ap, b0.y, acc[i][1]);
                acc[i][2] = f2(ap, b1.x, acc[i][2]);
                acc[i][3] = f2(ap, b1.y, acc[i][3]);
            }
        }
        __syncthreads();
    }
    int n0 = bn * 128 + tx * 8;
    float bb[8];
    #pragma unroll
    for (int j = 0; j < 8; j++) bb[j] = bias[n0 + j];
    #pragma unroll
    for (int i = 0; i < 8; i++) {
        int m = bm * 128 + ty * 8 + i;
        if (m < 3136) {
            float* dst = g_att1 + (size_t)m * 1024 + n0;
            #pragma unroll
            for (int j = 0; j < 4; j++) {
                float2 v = upk(acc[i][j]);
                dst[2 * j + 0] = v.x + bb[2 * j + 0];
                dst[2 * j + 1] = v.y + bb[2 * j + 1];
            }
        }
    }
}

// ================= per-step k2a: att2 + gate GEMV (+ emb fill) ============
// grid 128 blocks: block = 16 output cols (virtual N=2048: [att2|gate]), K=512
__global__ void __launch_bounds__(256)
k2a(const float* __restrict__ decW, const float* __restrict__ decB,
    const float* __restrict__ fbW, const float* __restrict__ fbB,
    const float* __restrict__ emb, int t) {
    __shared__ float s_red[16][16][16];   // [ks][c][b]
    int tid = threadIdx.x;
    int c = tid & 15, ks = tid >> 4;
    int c0 = blockIdx.x * 16;
    int col = c0 + c;
    const float* wptr = (col < 1024) ? (decW + (size_t)(ks * 32) * 1024 + col)
                                     : (fbW + (size_t)(ks * 32) * 1024 + (col - 1024));
    const float* xbase = g_xT + (1536 + ks * 32) * 16;
    ull acc[8];
    #pragma unroll
    for (int j = 0; j < 8; j++) acc[j] = 0ull;
    #pragma unroll 4
    for (int i = 0; i < 32; i++) {
        const ulonglong2* xr = (const ulonglong2*)(xbase + i * 16);
        ulonglong2 x0 = xr[0], x1 = xr[1], x2 = xr[2], x3 = xr[3];
        float w = wptr[(size_t)i * 1024];
        ull wb = pk(w, w);
        acc[0] = f2(x0.x, wb, acc[0]); acc[1] = f2(x0.y, wb, acc[1]);
        acc[2] = f2(x1.x, wb, acc[2]); acc[3] = f2(x1.y, wb, acc[3]);
        acc[4] = f2(x2.x, wb, acc[4]); acc[5] = f2(x2.y, wb, acc[5]);
        acc[6] = f2(x3.x, wb, acc[6]); acc[7] = f2(x3.y, wb, acc[7]);
    }
    #pragma unroll
    for (int j = 0; j < 8; j++) {
        float2 v = upk(acc[j]);
        s_red[ks][c][2 * j + 0] = v.x;
        s_red[ks][c][2 * j + 1] = v.y;
    }
    __syncthreads();
    {
        int c2 = tid >> 4, b = tid & 15;
        float s = 0.f;
        #pragma unroll
        for (int k = 0; k < 16; k++) s += s_red[k][c2][b];
        int ocol = c0 + c2;
        if (ocol < 1024) g_att2[b * 1024 + ocol] = s + decB[ocol];
        else             g_gate[b * 1024 + (ocol - 1024)] = sigmf(s + fbB[ocol - 1024]);
    }
    // tail: fill xT emb rows for this step (blocks 0..31 cover 16b x 512k)
    if (blockIdx.x < 32) {
        int idx = blockIdx.x * 256 + tid;
        int b = idx >> 9, k = idx & 511;
        int tok = g_caps[b * 32 + t];
        g_xT[k * 16 + b] = emb[(size_t)tok * 512 + k];
    }
}

// ================= per-step k2score: attention scores =====================
// grid 144 = 16 b x 9 p-chunks (22 p each)
__global__ void __launch_bounds__(256)
k2score(const float* __restrict__ fullW, const float* __restrict__ fullB) {
    __shared__ float att2s[1024], fw[1024];
    int tid = threadIdx.x;
    int b = blockIdx.x / 9, pc = blockIdx.x % 9;
    for (int j = tid; j < 1024; j += 256) {
        att2s[j] = g_att2[b * 1024 + j];
        fw[j] = fullW[j];
    }
    __syncthreads();
    int wid = tid >> 5, lane = tid & 31;
    int p0 = pc * 22;
    int pend = p0 + 22; if (pend > 196) pend = 196;
    float fb0 = fullB[0];
    for (int p = p0 + wid; p < pend; p += 8) {
        const float* row = g_att1 + (size_t)(b * 196 + p) * 1024;
        float acc = 0.f;
        #pragma unroll
        for (int eq = 0; eq < 8; eq++) {
            int e = eq * 128 + lane * 4;
            float4 x  = *(const float4*)(row + e);
            float4 a2 = *(const float4*)&att2s[e];
            float4 w  = *(const float4*)&fw[e];
            acc += fmaxf(x.x + a2.x, 0.f) * w.x;
            acc += fmaxf(x.y + a2.y, 0.f) * w.y;
            acc += fmaxf(x.z + a2.z, 0.f) * w.z;
            acc += fmaxf(x.w + a2.w, 0.f) * w.w;
        }
        #pragma unroll
        for (int o = 16; o > 0; o >>= 1) acc += __shfl_xor_sync(0xffffffffu, acc, o);
        if (lane == 0) g_att[b * 196 + p] = acc + fb0;
    }
}

// ================= per-step k2c: softmax + awe + alphas-out ===============
// grid 64 = 16 b x 4 e-chunks (256 e each); softmax recomputed per block
__global__ void __launch_bounds__(256)
k2c(const float* __restrict__ enc, float* __restrict__ out, int t) {
    __shared__ float s_al[200];
    __shared__ float s_red[8];
    __shared__ float s_b;
    int tid = threadIdx.x;
    int b = blockIdx.x >> 2, ec = blockIdx.x & 3;
    int wid = tid >> 5, lane = tid & 31;
    float sc = (tid < 196) ? g_att[b * 196 + tid] : -1e30f;
    float v = sc;
    #pragma unroll
    for (int o = 16; o > 0; o >>= 1) v = fmaxf(v, __shfl_xor_sync(0xffffffffu, v, o));
    if (lane == 0) s_red[wid] = v;
    __syncthreads();
    if (tid == 0) {
        float m = s_red[0];
        #pragma unroll
        for (int i = 1; i < 8; i++) m = fmaxf(m, s_red[i]);
        s_b = m;
    }
    __syncthreads();
    float mx = s_b;
    float ex = (tid < 196) ? expf(sc - mx) : 0.f;
    v = ex;
    #pragma unroll
    for (int o = 16; o > 0; o >>= 1) v += __shfl_xor_sync(0xffffffffu, v, o);
    if (lane == 0) s_red[wid] = v;
    __syncthreads();
    if (tid == 0) {
        float s = 0.f;
        #pragma unroll
        for (int i = 0; i < 8; i++) s += s_red[i];
        s_b = 1.0f / s;
    }
    __syncthreads();
    float alpha = ex * s_b;
    if (tid < 196) {
        s_al[tid] = alpha;
        if (ec == 0) {
            bool act = g_dlen[b] > t;
            out[OFF_ALPH + (size_t)(b * 31 + t) * 196 + tid] = act ? alpha : 0.f;
        }
    }
    __syncthreads();
    // awe for this e-chunk
    int e = ec * 256 + tid;
    const float* ep = enc + ((size_t)g_sort[b] * 196) * 1024 + e;
    float acc = 0.f;
    #pragma unroll 4
    for (int p = 0; p < 196; p++) acc += s_al[p] * ep[(size_t)p * 1024];
    g_xT[(512 + e) * 16 + b] = acc + g_gate[b * 1024 + e];
}

// ================= per-step k3: LSTM gates GEMM ===========================
// grid 128 blocks: 16 cols each, K=2048 split 16 ways in-block
__global__ void __launch_bounds__(256)
k3(const float* __restrict__ Wih, const float* __restrict__ bih,
   const float* __restrict__ Whh, const float* __restrict__ bhh) {
    __shared__ float s_red[16][16][16];
    int tid = threadIdx.x;
    int c = tid & 15, ks = tid >> 4;
    int c0 = blockIdx.x * 16;
    int col = c0 + c;
    const float* wptr = (ks < 12) ? (Wih + (size_t)(ks * 128) * 2048 + col)
                                  : (Whh + (size_t)((ks - 12) * 128) * 2048 + col);
    const float* xbase = g_xT + (ks * 128) * 16;
    ull acc[8];
    #pragma unroll
    for (int j = 0; j < 8; j++) acc[j] = 0ull;
    #pragma unroll 4
    for (int i = 0; i < 128; i++) {
        const ulonglong2* xr = (const ulonglong2*)(xbase + i * 16);
        ulonglong2 x0 = xr[0], x1 = xr[1], x2 = xr[2], x3 = xr[3];
        float w = wptr[(size_t)i * 2048];
        ull wb = pk(w, w);
        acc[0] = f2(x0.x, wb, acc[0]); acc[1] = f2(x0.y, wb, acc[1]);
        acc[2] = f2(x1.x, wb, acc[2]); acc[3] = f2(x1.y, wb, acc[3]);
        acc[4] = f2(x2.x, wb, acc[4]); acc[5] = f2(x2.y, wb, acc[5]);
        acc[6] = f2(x3.x, wb, acc[6]); acc[7] = f2(x3.y, wb, acc[7]);
    }
    #pragma unroll
    for (int j = 0; j < 8; j++) {
        float2 v = upk(acc[j]);
        s_red[ks][c][2 * j + 0] = v.x;
        s_red[ks][c][2 * j + 1] = v.y;
    }
    __syncthreads();
    int c2 = tid >> 4, b = tid & 15;
    float s = 0.f;
    #pragma unroll
    for (int k = 0; k < 16; k++) s += s_red[k][c2][b];
    int ocol = c0 + c2;
    g_gates[b * 2048 + ocol] = s + bih[ocol] + bhh[ocol];
}

// ================= per-step k3b: LSTM elementwise =========================
__global__ void k3b(int t) {
    int j = blockIdx.x * 256 + threadIdx.x;   // 8192 = 16 b x 512 d
    int b = j >> 9, d = j & 511;
    const float* gr = g_gates + b * 2048;
    float gi = gr[d], gf = gr[512 + d], gg = gr[1024 + d], go = gr[1536 + d];
    float cold = g_c[j];
    float cnew = sigmf(gf) * cold + sigmf(gi) * tanhf(gg);
    float hnew = sigmf(go) * tanhf(cnew);
    bool act = g_dlen[b] > t;
    float h2 = act ? hnew : g_h[j];
    float c2 = act ? cnew : cold;
    g_h[j] = h2;
    g_c[j] = c2;
    g_hT[d * 16 + b] = hnew;            // preds use h_new (unmasked)
    g_xT[(1536 + d) * 16 + b] = h2;     // next step's h input
}

// ================= per-step k4: vocab projection ==========================
// grid 313 blocks: 32 cols each, K=512 split 8 ways in-block
__global__ void __launch_bounds__(256)
k4(const float* __restrict__ fcW, const float* __restrict__ fcB,
   float* __restrict__ out, int t) {
    __shared__ float s_red[8][32][16];
    int tid = threadIdx.x;
    int c = tid & 31, ks = tid >> 5;
    int v0 = blockIdx.x * 32;
    int v = v0 + c;
    ull acc[8];
    #pragma unroll
    for (int j = 0; j < 8; j++) acc[j] = 0ull;
    if (v < 10000) {
        const float* wptr = fcW + (size_t)(ks * 64) * 10000 + v;
        const float* xbase = g_hT + (ks * 64) * 16;
        #pragma unroll 4
        for (int i = 0; i < 64; i++) {
            const ulonglong2* xr = (const ulonglong2*)(xbase + i * 16);
            ulonglong2 x0 = xr[0], x1 = xr[1], x2 = xr[2], x3 = xr[3];
            float w = wptr[(size_t)i * 10000];
            ull wb = pk(w, w);
            acc[0] = f2(x0.x, wb, acc[0]); acc[1] = f2(x0.y, wb, acc[1]);
            acc[2] = f2(x1.x, wb, acc[2]); acc[3] = f2(x1.y, wb, acc[3]);
            acc[4] = f2(x2.x, wb, acc[4]); acc[5] = f2(x2.y, wb, acc[5]);
            acc[6] = f2(x3.x, wb, acc[6]); acc[7] = f2(x3.y, wb, acc[7]);
        }
    }
    #pragma unroll
    for (int j = 0; j < 8; j++) {
        float2 vv = upk(acc[j]);
        s_red[ks][c][2 * j + 0] = vv.x;
        s_red[ks][c][2 * j + 1] = vv.y;
    }
    __syncthreads();
    #pragma unroll
    for (int r = 0; r < 2; r++) {
        int o = tid + r * 256;
        int c2 = o >> 4, b = o & 15;
        float s = 0.f;
        #pragma unroll
        for (int k = 0; k < 8; k++) s += s_red[k][c2][b];
        int vv = v0 + c2;
        if (vv < 10000) {
            bool act = g_dlen[b] > t;
            out[OFF_PRED + (size_t)(b * 31 + t) * 10000 + vv] =
                act ? (s + fcB[vv]) : 0.f;
        }
    }
}

// ================= launcher ==============================================
extern "C" void kernel_launch(void* const* d_in, const int* in_sizes, int n_in,
                              void* d_out, int out_size) {
    const float* enc    = (const float*)d_in[0];
    const float* encW   = (const float*)d_in[1];
    const float* encB   = (const float*)d_in[2];
    const float* decW   = (const float*)d_in[3];
    const float* decB   = (const float*)d_in[4];
    const float* fullW  = (const float*)d_in[5];
    const float* fullB  = (const float*)d_in[6];
    const float* emb    = (const float*)d_in[7];
    const float* Wih    = (const float*)d_in[8];
    const float* bih    = (const float*)d_in[9];
    const float* Whh    = (const float*)d_in[10];
    const float* bhh    = (const float*)d_in[11];
    const float* ihW    = (const float*)d_in[12];
    const float* ihB    = (const float*)d_in[13];
    const float* icW    = (const float*)d_in[14];
    const float* icB    = (const float*)d_in[15];
    const float* fbW    = (const float*)d_in[16];
    const float* fbB    = (const float*)d_in[17];
    const float* fcW    = (const float*)d_in[18];
    const float* fcB    = (const float*)d_in[19];
    const int*   capsin = (const int*)d_in[20];
    const int*   clen   = (const int*)d_in[21];
    float* out = (float*)d_out;

    ksetup1<<<1, 256>>>(capsin, clen, out);
    ksetup2<<<64, 256>>>(enc);
    ksetup3<<<64, 256>>>(ihW, ihB, icW, icB);
    katt1<<<dim3(8, 25), 256>>>(enc, encW, encB);

    for (int t = 0; t < 31; t++) {
        k2a<<<128, 256>>>(decW, decB, fbW, fbB, emb, t);
        k2score<<<144, 256>>>(fullW, fullB);
        k2c<<<64, 256>>>(enc, out, t);
        k3<<<128, 256>>>(Wih, bih, Whh, bhh);
        k3b<<<32, 256>>>(t);
        k4<<<313, 256>>>(fcW, fcB, out, t);
    }
}

// round 3
// speedup vs baseline: 1.4842x; 1.4842x over previous
#include <cuda_runtime.h>
#include <cstdint>
#include <cstddef>

typedef unsigned long long ull;

// ---------------- output layout (float32 concat of reference tuple) -------
#define OFF_PRED 0
#define OFF_CAPS 4960000
#define OFF_DLEN 4960512
#define OFF_ALPH 4960528
#define OFF_SORT 5057744

#define NBLK 148

// ---------------- device scratch (static globals: no allocs) --------------
__device__ int   g_sort[16], g_dlen[16], g_caps[512];
__device__ float g_mean[16 * 1024];
__device__ float g_att1[3136 * 1024];     // 12.8 MB
__device__ float g_h[16 * 512], g_c[16 * 512];
__device__ float g_hT[512 * 16];          // h_new transposed [d][b]
__device__ float g_xT[2048 * 16];         // X transposed [k][b]: emb|awe|h
__device__ float g_att2[16 * 1024], g_gate[16 * 1024];
__device__ float g_att[3136];
__device__ float g_gates[16 * 2048];
__device__ unsigned g_cnt = 0, g_gen = 0;

// ---------------- helpers ----------------
__device__ __forceinline__ ull pk(float x, float y) {
    ull u; asm("mov.b64 %0,{%1,%2};" : "=l"(u) : "f"(x), "f"(y)); return u;
}
__device__ __forceinline__ float2 upk(ull u) {
    float2 v; asm("mov.b64 {%0,%1},%2;" : "=f"(v.x), "=f"(v.y) : "l"(u)); return v;
}
__device__ __forceinline__ ull f2(ull a, ull b, ull c) {
    ull d; asm("fma.rn.f32x2 %0,%1,%2,%3;" : "=l"(d) : "l"(a), "l"(b), "l"(c)); return d;
}
__device__ __forceinline__ float sigmf(float x) { return 1.f / (1.f + expf(-x)); }

// ================= setup 1: stable sort + caps/dlen/sort_ind out ==========
__global__ void ksetup1(const int* __restrict__ caps_in,
                        const int* __restrict__ clen,
                        float* __restrict__ out) {
    int tid = threadIdx.x;
    if (tid == 0) {
        int len[16];
        #pragma unroll
        for (int i = 0; i < 16; i++) len[i] = clen[i];
        for (int i = 0; i < 16; i++) {
            int rank = 0;
            for (int j = 0; j < 16; j++)
                rank += (len[j] > len[i]) || (len[j] == len[i] && j < i);
            g_sort[rank] = i;
            g_dlen[rank] = len[i] - 1;
            out[OFF_SORT + rank] = (float)i;
            out[OFF_DLEN + rank] = (float)(len[i] - 1);
        }
    }
    __syncthreads();
    for (int j = tid; j < 512; j += 256) {
        int b = j >> 5, l = j & 31;
        int v = caps_in[g_sort[b] * 32 + l];
        g_caps[j] = v;
        out[OFF_CAPS + j] = (float)v;
    }
}

// ================= setup 2: mean over P of sorted encoder ==================
__global__ void ksetup2(const float* __restrict__ enc) {
    int j = blockIdx.x * 256 + threadIdx.x;   // 16384 = 16 b x 1024 e
    int b = j >> 10, e = j & 1023;
    const float* p0 = enc + ((size_t)g_sort[b] * 196) * 1024 + e;
    float s = 0.f;
    #pragma unroll 8
    for (int p = 0; p < 196; p++) s += p0[(size_t)p * 1024];
    g_mean[j] = s * (1.0f / 196.0f);
}

// ================= setup 3: h0, c0 (also fill xT h-rows) ===================
__global__ void ksetup3(const float* __restrict__ ihW, const float* __restrict__ ihB,
                        const float* __restrict__ icW, const float* __restrict__ icB) {
    int j = blockIdx.x * 256 + threadIdx.x;   // 16384 = 2 x 16 b x 512 d
    int which = j >> 13;
    int jj = j & 8191;
    int b = jj >> 9, d = jj & 511;
    const float* W = which ? icW : ihW;
    const float* mrow = g_mean + b * 1024;
    float acc = 0.f;
    #pragma unroll 8
    for (int k = 0; k < 1024; k++) acc += mrow[k] * W[k * 512 + d];
    float val = acc + (which ? icB[d] : ihB[d]);
    if (which) g_c[b * 512 + d] = val;
    else { g_h[b * 512 + d] = val; g_xT[(1536 + d) * 16 + b] = val; }
}

// ================= att1 GEMM: (3136x1024) = enc_sorted @ encW + b =========
// 128x128 tile, 256 threads, 8x8 micro, f32x2 accumulation, reg-prefetch
__global__ void __launch_bounds__(256, 1)
katt1(const float* __restrict__ enc, const float* __restrict__ W,
      const float* __restrict__ bias) {
    __shared__ float As[32][132];   // transposed A: As[k][m]
    __shared__ float Bs[32][128];
    int tid = threadIdx.x;
    int bm = blockIdx.y, bn = blockIdx.x;

    int kq = tid & 7, ml = tid >> 3;
    const float* arow[4];
    #pragma unroll
    for (int ps = 0; ps < 4; ps++) {
        int m = bm * 128 + ml + ps * 32;
        int mc = m < 3135 ? m : 3135;
        int b = mc / 196, p = mc - b * 196;
        arow[ps] = enc + ((size_t)g_sort[b] * 196 + p) * 1024 + kq * 4;
    }
    int nb = tid & 31, kb = tid >> 5;
    const float* bptr = W + (size_t)kb * 1024 + bn * 128 + nb * 4;

    ull acc[8][4];
    #pragma unroll
    for (int i = 0; i < 8; i++)
        #pragma unroll
        for (int j = 0; j < 4; j++) acc[i][j] = 0ull;

    int tx = tid & 15, ty = tid >> 4;

    // prefetch tile 0 into regs
    float4 ra[4], rb[4];
    #pragma unroll
    for (int ps = 0; ps < 4; ps++) ra[ps] = *(const float4*)(arow[ps]);
    #pragma unroll
    for (int ps = 0; ps < 4; ps++) rb[ps] = *(const float4*)(bptr + (size_t)(ps * 8) * 1024);

    for (int kt = 0; kt < 1024; kt += 32) {
        // store regs -> smem
        #pragma unroll
        for (int ps = 0; ps < 4; ps++) {
            int mm = ml + ps * 32;
            As[kq * 4 + 0][mm] = ra[ps].x;
            As[kq * 4 + 1][mm] = ra[ps].y;
            As[kq * 4 + 2][mm] = ra[ps].z;
            As[kq * 4 + 3][mm] = ra[ps].w;
        }
        #pragma unroll
        for (int ps = 0; ps < 4; ps++)
            *(float4*)&Bs[kb + ps * 8][nb * 4] = rb[ps];
        __syncthreads();
        // issue next-tile loads early (overlap with compute)
        if (kt + 32 < 1024) {
            #pragma unroll
            for (int ps = 0; ps < 4; ps++)
                ra[ps] = *(const float4*)(arow[ps] + kt + 32);
            #pragma unroll
            for (int ps = 0; ps < 4; ps++)
                rb[ps] = *(const float4*)(bptr + (size_t)(kt + 32 + ps * 8) * 1024);
        }
        #pragma unroll 8
        for (int kk = 0; kk < 32; kk++) {
            float4 a0 = *(const float4*)&As[kk][ty * 8];
            float4 a1 = *(const float4*)&As[kk][ty * 8 + 4];
            ulonglong2 b0 = *(const ulonglong2*)&Bs[kk][tx * 8];
            ulonglong2 b1 = *(const ulonglong2*)&Bs[kk][tx * 8 + 4];
            float a[8] = {a0.x, a0.y, a0.z, a0.w, a1.x, a1.y, a1.z, a1.w};
            #pragma unroll
            for (int i = 0; i < 8; i++) {
                ull ap = pk(a[i], a[i]);
                acc[i][0] = f2(ap, b0.x, acc[i][0]);
                acc[i][1] = f2(ap, b0.y, acc[i][1]);
                acc[i][2] = f2(ap, b1.x, acc[i][2]);
                acc[i][3] = f2(ap, b1.y, acc[i][3]);
            }
        }
        __syncthreads();
    }
    int n0 = bn * 128 + tx * 8;
    float bb[8];
    #pragma unroll
    for (int j = 0; j < 8; j++) bb[j] = bias[n0 + j];
    #pragma unroll
    for (int i = 0; i < 8; i++) {
        int m = bm * 128 + ty * 8 + i;
        if (m < 3136) {
            float* dst = g_att1 + (size_t)m * 1024 + n0;
            #pragma unroll
            for (int j = 0; j < 4; j++) {
                float2 v = upk(acc[i][j]);
                dst[2 * j + 0] = v.x + bb[2 * j + 0];
                dst[2 * j + 1] = v.y + bb[2 * j + 1];
            }
        }
    }
}

// ================= persistent step kernel ==================================
__global__ void __launch_bounds__(256, 1)
kstep(const float* __restrict__ enc,
      const float* __restrict__ decW, const float* __restrict__ decB,
      const float* __restrict__ fullW, const float* __restrict__ fullB,
      const float* __restrict__ fbW, const float* __restrict__ fbB,
      const float* __restrict__ emb,
      const float* __restrict__ Wih, const float* __restrict__ bih,
      const float* __restrict__ Whh, const float* __restrict__ bhh,
      const float* __restrict__ fcW, const float* __restrict__ fcB,
      float* __restrict__ out)
{
    __shared__ float sbuf[4096];   // 16KB, reused per phase
    const int tid = threadIdx.x;
    const int bid = blockIdx.x;
    unsigned mygen = *(volatile unsigned*)&g_gen;

#define GRIDBAR() do {                                                   \
    __syncthreads();                                                     \
    if (tid == 0) {                                                      \
        __threadfence();                                                 \
        if (atomicAdd(&g_cnt, 1u) == gridDim.x - 1) {                    \
            g_cnt = 0;                                                   \
            __threadfence();                                             \
            *(volatile unsigned*)&g_gen = mygen + 1;                     \
        } else {                                                         \
            while (*(volatile unsigned*)&g_gen == mygen) { }             \
            __threadfence();                                             \
        }                                                                \
    }                                                                    \
    mygen++;                                                             \
    __syncthreads();                                                     \
} while (0)

    // -------- phase E: vocab projection for step tp (reads g_hT) --------
    auto phaseE = [&](int tp) {
        float (*s_red)[32][16] = (float(*)[32][16])sbuf;
        for (int ch = bid; ch < 313; ch += NBLK) {
            int c = tid & 31, ks = tid >> 5;
            int v0 = ch * 32;
            int v = v0 + c;
            ull acc[8];
            #pragma unroll
            for (int j = 0; j < 8; j++) acc[j] = 0ull;
            if (v < 10000) {
                const float* wptr = fcW + (size_t)(ks * 64) * 10000 + v;
                const float* xbase = g_hT + (ks * 64) * 16;
                #pragma unroll 4
                for (int i = 0; i < 64; i++) {
                    const ulonglong2* xr = (const ulonglong2*)(xbase + i * 16);
                    ulonglong2 x0 = xr[0], x1 = xr[1], x2 = xr[2], x3 = xr[3];
                    float w = wptr[(size_t)i * 10000];
                    ull wb = pk(w, w);
                    acc[0] = f2(x0.x, wb, acc[0]); acc[1] = f2(x0.y, wb, acc[1]);
                    acc[2] = f2(x1.x, wb, acc[2]); acc[3] = f2(x1.y, wb, acc[3]);
                    acc[4] = f2(x2.x, wb, acc[4]); acc[5] = f2(x2.y, wb, acc[5]);
                    acc[6] = f2(x3.x, wb, acc[6]); acc[7] = f2(x3.y, wb, acc[7]);
                }
            }
            #pragma unroll
            for (int j = 0; j < 8; j++) {
                float2 vv = upk(acc[j]);
                s_red[ks][c][2 * j + 0] = vv.x;
                s_red[ks][c][2 * j + 1] = vv.y;
            }
            __syncthreads();
            #pragma unroll
            for (int r = 0; r < 2; r++) {
                int o = tid + r * 256;
                int c2 = o >> 4, b = o & 15;
                float s = 0.f;
                #pragma unroll
                for (int k = 0; k < 8; k++) s += s_red[k][c2][b];
                int vv = v0 + c2;
                if (vv < 10000) {
                    bool act = g_dlen[b] > tp;
                    out[OFF_PRED + (size_t)(b * 31 + tp) * 10000 + vv] =
                        act ? (s + fcB[vv]) : 0.f;
                }
            }
            __syncthreads();
        }
    };

    for (int t = 0; t < 31; t++) {
        // ============ Segment 1: E(t-1) + A(t) + emb fill =================
        if (t > 0) phaseE(t - 1);
        __syncthreads();
        if (bid < 128) {
            // phase A: att2 + gate GEMV (virtual N=2048, K=512)
            float (*s_red)[16][16] = (float(*)[16][16])sbuf;
            int c = tid & 15, ks = tid >> 4;
            int c0 = bid * 16;
            int col = c0 + c;
            const float* wptr = (col < 1024)
                ? (decW + (size_t)(ks * 32) * 1024 + col)
                : (fbW + (size_t)(ks * 32) * 1024 + (col - 1024));
            const float* xbase = g_xT + (1536 + ks * 32) * 16;
            ull acc[8];
            #pragma unroll
            for (int j = 0; j < 8; j++) acc[j] = 0ull;
            #pragma unroll 4
            for (int i = 0; i < 32; i++) {
                const ulonglong2* xr = (const ulonglong2*)(xbase + i * 16);
                ulonglong2 x0 = xr[0], x1 = xr[1], x2 = xr[2], x3 = xr[3];
                float w = wptr[(size_t)i * 1024];
                ull wb = pk(w, w);
                acc[0] = f2(x0.x, wb, acc[0]); acc[1] = f2(x0.y, wb, acc[1]);
                acc[2] = f2(x1.x, wb, acc[2]); acc[3] = f2(x1.y, wb, acc[3]);
                acc[4] = f2(x2.x, wb, acc[4]); acc[5] = f2(x2.y, wb, acc[5]);
                acc[6] = f2(x3.x, wb, acc[6]); acc[7] = f2(x3.y, wb, acc[7]);
            }
            #pragma unroll
            for (int j = 0; j < 8; j++) {
                float2 v = upk(acc[j]);
                s_red[ks][c][2 * j + 0] = v.x;
                s_red[ks][c][2 * j + 1] = v.y;
            }
            __syncthreads();
            int c2 = tid >> 4, b = tid & 15;
            float s = 0.f;
            #pragma unroll
            for (int k = 0; k < 16; k++) s += s_red[k][c2][b];
            int ocol = c0 + c2;
            if (ocol < 1024) g_att2[b * 1024 + ocol] = s + decB[ocol];
            else             g_gate[b * 1024 + (ocol - 1024)] = sigmf(s + fbB[ocol - 1024]);
        } else {
            // emb fill: 8192 = 16b x 512k over blocks 128..147
            for (int j = (bid - 128) * 256 + tid; j < 8192; j += 20 * 256) {
                int b = j >> 9, k = j & 511;
                int tok = g_caps[b * 32 + t];
                g_xT[k * 16 + b] = emb[(size_t)tok * 512 + k];
            }
        }
        GRIDBAR();

        // ============ Segment 2: attention scores =========================
        {
            float* fw = sbuf;
            for (int j = tid; j < 1024; j += 256) fw[j] = fullW[j];
            __syncthreads();
            float fb0 = fullB[0];
            int lane = tid & 31;
            int gw = bid * 8 + (tid >> 5);
            for (int r = gw; r < 3136; r += NBLK * 8) {
                int b = r / 196;
                const float* row = g_att1 + (size_t)r * 1024;
                const float* a2r = g_att2 + b * 1024;
                float acc = 0.f;
                #pragma unroll
                for (int eq = 0; eq < 8; eq++) {
                    int e = eq * 128 + lane * 4;
                    float4 x  = *(const float4*)(row + e);
                    float4 a2 = *(const float4*)(a2r + e);
                    float4 w  = *(const float4*)&fw[e];
                    acc += fmaxf(x.x + a2.x, 0.f) * w.x;
                    acc += fmaxf(x.y + a2.y, 0.f) * w.y;
                    acc += fmaxf(x.z + a2.z, 0.f) * w.z;
                    acc += fmaxf(x.w + a2.w, 0.f) * w.w;
                }
                #pragma unroll
                for (int o = 16; o > 0; o >>= 1)
                    acc += __shfl_xor_sync(0xffffffffu, acc, o);
                if (lane == 0) g_att[r] = acc + fb0;
            }
        }
        GRIDBAR();

        // ============ Segment 3: softmax + awe + alphas ===================
        if (bid < 128) {
            float* s_al = sbuf;            // [0..199]
            float* s_rd = sbuf + 200;      // [200..207]
            float* s_sc = sbuf + 216;      // scalar
            float* s_aw = sbuf + 256;      // [256..383]
            int b = bid >> 3, ec = bid & 7;
            int wid = tid >> 5, lane = tid & 31;
            float sc = (tid < 196) ? g_att[b * 196 + tid] : -1e30f;
            float v = sc;
            #pragma unroll
            for (int o = 16; o > 0; o >>= 1)
                v = fmaxf(v, __shfl_xor_sync(0xffffffffu, v, o));
            if (lane == 0) s_rd[wid] = v;
            __syncthreads();
            if (tid == 0) {
                float m = s_rd[0];
                #pragma unroll
                for (int i = 1; i < 8; i++) m = fmaxf(m, s_rd[i]);
                s_sc[0] = m;
            }
            __syncthreads();
            float mx = s_sc[0];
            float ex = (tid < 196) ? expf(sc - mx) : 0.f;
            v = ex;
            #pragma unroll
            for (int o = 16; o > 0; o >>= 1)
                v += __shfl_xor_sync(0xffffffffu, v, o);
            if (lane == 0) s_rd[wid] = v;
            __syncthreads();
            if (tid == 0) {
                float s = 0.f;
                #pragma unroll
                for (int i = 0; i < 8; i++) s += s_rd[i];
                s_sc[0] = 1.0f / s;
            }
            __syncthreads();
            float alpha = ex * s_sc[0];
            if (tid < 196) {
                s_al[tid] = alpha;
                if (ec == 0) {
                    bool act = g_dlen[b] > t;
                    out[OFF_ALPH + (size_t)(b * 31 + t) * 196 + tid] = act ? alpha : 0.f;
                }
            }
            __syncthreads();
            // awe: 128 e per unit, p split in half across thread halves
            int el = tid & 127;
            int e = ec * 128 + el;
            int ph = tid >> 7;
            int p0 = ph * 98;
            const float* ep = enc + ((size_t)g_sort[b] * 196 + p0) * 1024 + e;
            float acc = 0.f;
            #pragma unroll 14
            for (int p = 0; p < 98; p++)
                acc += s_al[p0 + p] * ep[(size_t)p * 1024];
            if (ph) s_aw[el] = acc;
            __syncthreads();
            if (!ph) {
                float tot = acc + s_aw[el];
                g_xT[(512 + e) * 16 + b] = tot + g_gate[b * 1024 + e];
            }
        }
        GRIDBAR();

        // ============ Segment 4: LSTM gates GEMM ==========================
        if (bid < 128) {
            float (*s_red)[16][16] = (float(*)[16][16])sbuf;
            int c = tid & 15, ks = tid >> 4;
            int c0 = bid * 16;
            int col = c0 + c;
            const float* wptr = (ks < 12)
                ? (Wih + (size_t)(ks * 128) * 2048 + col)
                : (Whh + (size_t)((ks - 12) * 128) * 2048 + col);
            const float* xbase = g_xT + (ks * 128) * 16;
            ull acc[8];
            #pragma unroll
            for (int j = 0; j < 8; j++) acc[j] = 0ull;
            #pragma unroll 4
            for (int i = 0; i < 128; i++) {
                const ulonglong2* xr = (const ulonglong2*)(xbase + i * 16);
                ulonglong2 x0 = xr[0], x1 = xr[1], x2 = xr[2], x3 = xr[3];
                float w = wptr[(size_t)i * 2048];
                ull wb = pk(w, w);
                acc[0] = f2(x0.x, wb, acc[0]); acc[1] = f2(x0.y, wb, acc[1]);
                acc[2] = f2(x1.x, wb, acc[2]); acc[3] = f2(x1.y, wb, acc[3]);
                acc[4] = f2(x2.x, wb, acc[4]); acc[5] = f2(x2.y, wb, acc[5]);
                acc[6] = f2(x3.x, wb, acc[6]); acc[7] = f2(x3.y, wb, acc[7]);
            }
            #pragma unroll
            for (int j = 0; j < 8; j++) {
                float2 v = upk(acc[j]);
                s_red[ks][c][2 * j + 0] = v.x;
                s_red[ks][c][2 * j + 1] = v.y;
            }
            __syncthreads();
            int c2 = tid >> 4, b = tid & 15;
            float s = 0.f;
            #pragma unroll
            for (int k = 0; k < 16; k++) s += s_red[k][c2][b];
            int ocol = c0 + c2;
            g_gates[b * 2048 + ocol] = s + bih[ocol] + bhh[ocol];
        }
        GRIDBAR();

        // ============ Segment 5: LSTM elementwise =========================
        {
            int gid = bid * 256 + tid;
            if (gid < 8192) {
                int b = gid >> 9, d = gid & 511;
                const float* gr = g_gates + b * 2048;
                float gi = gr[d], gf = gr[512 + d], gg = gr[1024 + d], go = gr[1536 + d];
                float cold = g_c[gid];
                float cnew = sigmf(gf) * cold + sigmf(gi) * tanhf(gg);
                float hnew = sigmf(go) * tanhf(cnew);
                bool act = g_dlen[b] > t;
                float h2 = act ? hnew : g_h[gid];
                float c2v = act ? cnew : cold;
                g_h[gid] = h2;
                g_c[gid] = c2v;
                g_hT[d * 16 + b] = hnew;
                g_xT[(1536 + d) * 16 + b] = h2;
            }
        }
        GRIDBAR();
    }

    // final vocab projection for t = 30
    phaseE(30);
#undef GRIDBAR
}

// ================= launcher ==============================================
extern "C" void kernel_launch(void* const* d_in, const int* in_sizes, int n_in,
                              void* d_out, int out_size) {
    const float* enc    = (const float*)d_in[0];
    const float* encW   = (const float*)d_in[1];
    const float* encB   = (const float*)d_in[2];
    const float* decW   = (const float*)d_in[3];
    const float* decB   = (const float*)d_in[4];
    const float* fullW  = (const float*)d_in[5];
    const float* fullB  = (const float*)d_in[6];
    const float* emb    = (const float*)d_in[7];
    const float* Wih    = (const float*)d_in[8];
    const float* bih    = (const float*)d_in[9];
    const float* Whh    = (const float*)d_in[10];
    const float* bhh    = (const float*)d_in[11];
    const float* ihW    = (const float*)d_in[12];
    const float* ihB    = (const float*)d_in[13];
    const float* icW    = (const float*)d_in[14];
    const float* icB    = (const float*)d_in[15];
    const float* fbW    = (const float*)d_in[16];
    const float* fbB    = (const float*)d_in[17];
    const float* fcW    = (const float*)d_in[18];
    const float* fcB    = (const float*)d_in[19];
    const int*   capsin = (const int*)d_in[20];
    const int*   clen   = (const int*)d_in[21];
    float* out = (float*)d_out;

    ksetup1<<<1, 256>>>(capsin, clen, out);
    ksetup2<<<64, 256>>>(enc);
    ksetup3<<<64, 256>>>(ihW, ihB, icW, icB);
    katt1<<<dim3(8, 25), 256>>>(enc, encW, encB);
    kstep<<<NBLK, 256>>>(enc, decW, decB, fullW, fullB, fbW, fbB, emb,
                         Wih, bih, Whh, bhh, fcW, fcB, out);
}

// round 4
// speedup vs baseline: 1.7362x; 1.1698x over previous
#include <cuda_runtime.h>
#include <cstdint>
#include <cstddef>

typedef unsigned long long ull;

// ---------------- output layout (float32 concat of reference tuple) -------
#define OFF_PRED 0
#define OFF_CAPS 4960000
#define OFF_DLEN 4960512
#define OFF_ALPH 4960528
#define OFF_SORT 5057744

#define NBLK 148

// ---------------- device scratch (static globals: no allocs) --------------
__device__ int   g_sort[16], g_dlen[16], g_caps[512];
__device__ float g_mean[16 * 1024];
__device__ float g_att1[3136 * 1024];     // 12.8 MB
__device__ float g_h[16 * 512], g_c[16 * 512];
__device__ float g_hT[512 * 16];          // h_new transposed [d][b]
__device__ float g_xT[2048 * 16];         // X transposed [k][b]: emb|awe|h
__device__ float g_att2[16 * 1024], g_gate[16 * 1024];
__device__ unsigned g_cnt = 0, g_gen = 0;       // full barrier
__device__ unsigned g_cntA = 0, g_genA = 0;     // partial (64-block) barrier

// ---------------- helpers ----------------
__device__ __forceinline__ ull pk(float x, float y) {
    ull u; asm("mov.b64 %0,{%1,%2};" : "=l"(u) : "f"(x), "f"(y)); return u;
}
__device__ __forceinline__ float2 upk(ull u) {
    float2 v; asm("mov.b64 {%0,%1},%2;" : "=f"(v.x), "=f"(v.y) : "l"(u)); return v;
}
__device__ __forceinline__ ull f2(ull a, ull b, ull c) {
    ull d; asm("fma.rn.f32x2 %0,%1,%2,%3;" : "=l"(d) : "l"(a), "l"(b), "l"(c)); return d;
}
__device__ __forceinline__ float sigmf(float x) { return 1.f / (1.f + expf(-x)); }

__device__ __forceinline__ void bar_sync(unsigned* cnt, unsigned* gen,
                                         unsigned count, unsigned& mygen) {
    __syncthreads();
    if (threadIdx.x == 0) {
        __threadfence();
        if (atomicAdd(cnt, 1u) == count - 1) {
            *cnt = 0;
            __threadfence();
            *(volatile unsigned*)gen = mygen + 1;
        } else {
            while (*(volatile unsigned*)gen == mygen) { }
            __threadfence();
        }
    }
    mygen++;
    __syncthreads();
}

// ================= setup 1: stable sort + caps/dlen/sort_ind out ==========
__global__ void ksetup1(const int* __restrict__ caps_in,
                        const int* __restrict__ clen,
                        float* __restrict__ out) {
    int tid = threadIdx.x;
    if (tid == 0) {
        int len[16];
        #pragma unroll
        for (int i = 0; i < 16; i++) len[i] = clen[i];
        for (int i = 0; i < 16; i++) {
            int rank = 0;
            for (int j = 0; j < 16; j++)
                rank += (len[j] > len[i]) || (len[j] == len[i] && j < i);
            g_sort[rank] = i;
            g_dlen[rank] = len[i] - 1;
            out[OFF_SORT + rank] = (float)i;
            out[OFF_DLEN + rank] = (float)(len[i] - 1);
        }
    }
    __syncthreads();
    for (int j = tid; j < 512; j += 256) {
        int b = j >> 5, l = j & 31;
        int v = caps_in[g_sort[b] * 32 + l];
        g_caps[j] = v;
        out[OFF_CAPS + j] = (float)v;
    }
}

// ================= setup 2: mean over P of sorted encoder ==================
__global__ void ksetup2(const float* __restrict__ enc) {
    int j = blockIdx.x * 256 + threadIdx.x;   // 16384 = 16 b x 1024 e
    int b = j >> 10, e = j & 1023;
    const float* p0 = enc + ((size_t)g_sort[b] * 196) * 1024 + e;
    float s = 0.f;
    #pragma unroll 8
    for (int p = 0; p < 196; p++) s += p0[(size_t)p * 1024];
    g_mean[j] = s * (1.0f / 196.0f);
}

// ================= setup 3: h0, c0 (also fill xT h-rows) ===================
__global__ void ksetup3(const float* __restrict__ ihW, const float* __restrict__ ihB,
                        const float* __restrict__ icW, const float* __restrict__ icB) {
    int j = blockIdx.x * 256 + threadIdx.x;   // 16384 = 2 x 16 b x 512 d
    int which = j >> 13;
    int jj = j & 8191;
    int b = jj >> 9, d = jj & 511;
    const float* W = which ? icW : ihW;
    const float* mrow = g_mean + b * 1024;
    float acc = 0.f;
    #pragma unroll 8
    for (int k = 0; k < 1024; k++) acc += mrow[k] * W[k * 512 + d];
    float val = acc + (which ? icB[d] : ihB[d]);
    if (which) g_c[b * 512 + d] = val;
    else { g_h[b * 512 + d] = val; g_xT[(1536 + d) * 16 + b] = val; }
}

// ================= att1 GEMM (unchanged from R3) ===========================
__global__ void __launch_bounds__(256, 1)
katt1(const float* __restrict__ enc, const float* __restrict__ W,
      const float* __restrict__ bias) {
    __shared__ float As[32][132];
    __shared__ float Bs[32][128];
    int tid = threadIdx.x;
    int bm = blockIdx.y, bn = blockIdx.x;

    int kq = tid & 7, ml = tid >> 3;
    const float* arow[4];
    #pragma unroll
    for (int ps = 0; ps < 4; ps++) {
        int m = bm * 128 + ml + ps * 32;
        int mc = m < 3135 ? m : 3135;
        int b = mc / 196, p = mc - b * 196;
        arow[ps] = enc + ((size_t)g_sort[b] * 196 + p) * 1024 + kq * 4;
    }
    int nb = tid & 31, kb = tid >> 5;
    const float* bptr = W + (size_t)kb * 1024 + bn * 128 + nb * 4;

    ull acc[8][4];
    #pragma unroll
    for (int i = 0; i < 8; i++)
        #pragma unroll
        for (int j = 0; j < 4; j++) acc[i][j] = 0ull;

    int tx = tid & 15, ty = tid >> 4;

    float4 ra[4], rb[4];
    #pragma unroll
    for (int ps = 0; ps < 4; ps++) ra[ps] = *(const float4*)(arow[ps]);
    #pragma unroll
    for (int ps = 0; ps < 4; ps++) rb[ps] = *(const float4*)(bptr + (size_t)(ps * 8) * 1024);

    for (int kt = 0; kt < 1024; kt += 32) {
        #pragma unroll
        for (int ps = 0; ps < 4; ps++) {
            int mm = ml + ps * 32;
            As[kq * 4 + 0][mm] = ra[ps].x;
            As[kq * 4 + 1][mm] = ra[ps].y;
            As[kq * 4 + 2][mm] = ra[ps].z;
            As[kq * 4 + 3][mm] = ra[ps].w;
        }
        #pragma unroll
        for (int ps = 0; ps < 4; ps++)
            *(float4*)&Bs[kb + ps * 8][nb * 4] = rb[ps];
        __syncthreads();
        if (kt + 32 < 1024) {
            #pragma unroll
            for (int ps = 0; ps < 4; ps++)
                ra[ps] = *(const float4*)(arow[ps] + kt + 32);
            #pragma unroll
            for (int ps = 0; ps < 4; ps++)
                rb[ps] = *(const float4*)(bptr + (size_t)(kt + 32 + ps * 8) * 1024);
        }
        #pragma unroll 8
        for (int kk = 0; kk < 32; kk++) {
            float4 a0 = *(const float4*)&As[kk][ty * 8];
            float4 a1 = *(const float4*)&As[kk][ty * 8 + 4];
            ulonglong2 b0 = *(const ulonglong2*)&Bs[kk][tx * 8];
            ulonglong2 b1 = *(const ulonglong2*)&Bs[kk][tx * 8 + 4];
            float a[8] = {a0.x, a0.y, a0.z, a0.w, a1.x, a1.y, a1.z, a1.w};
            #pragma unroll
            for (int i = 0; i < 8; i++) {
                ull ap = pk(a[i], a[i]);
                acc[i][0] = f2(ap, b0.x, acc[i][0]);
                acc[i][1] = f2(ap, b0.y, acc[i][1]);
                acc[i][2] = f2(ap, b1.x, acc[i][2]);
                acc[i][3] = f2(ap, b1.y, acc[i][3]);
            }
        }
        __syncthreads();
    }
    int n0 = bn * 128 + tx * 8;
    float bb[8];
    #pragma unroll
    for (int j = 0; j < 8; j++) bb[j] = bias[n0 + j];
    #pragma unroll
    for (int i = 0; i < 8; i++) {
        int m = bm * 128 + ty * 8 + i;
        if (m < 3136) {
            float* dst = g_att1 + (size_t)m * 1024 + n0;
            #pragma unroll
            for (int j = 0; j < 4; j++) {
                float2 v = upk(acc[i][j]);
                dst[2 * j + 0] = v.x + bb[2 * j + 0];
                dst[2 * j + 1] = v.y + bb[2 * j + 1];
            }
        }
    }
}

// ================= persistent step kernel ==================================
__global__ void __launch_bounds__(256, 1)
kstep(const float* __restrict__ enc,
      const float* __restrict__ decW, const float* __restrict__ decB,
      const float* __restrict__ fullW, const float* __restrict__ fullB,
      const float* __restrict__ fbW, const float* __restrict__ fbB,
      const float* __restrict__ emb,
      const float* __restrict__ Wih, const float* __restrict__ bih,
      const float* __restrict__ Whh, const float* __restrict__ bhh,
      const float* __restrict__ fcW, const float* __restrict__ fcB,
      float* __restrict__ out)
{
    __shared__ float sbuf[4608];   // 18KB, reused per phase
    const int tid = threadIdx.x;
    const int bid = blockIdx.x;
    unsigned mygen  = *(volatile unsigned*)&g_gen;
    unsigned mygenA = *(volatile unsigned*)&g_genA;

    // -------- phase E: vocab projection for step tp (reads g_hT) --------
    auto phaseE = [&](int tp, int start, int stride) {
        float (*s_red)[32][16] = (float(*)[32][16])sbuf;
        for (int ch = start; ch < 313; ch += stride) {
            int c = tid & 31, ks = tid >> 5;
            int v0 = ch * 32;
            int v = v0 + c;
            ull acc[8];
            #pragma unroll
            for (int j = 0; j < 8; j++) acc[j] = 0ull;
            if (v < 10000) {
                const float* wptr = fcW + (size_t)(ks * 64) * 10000 + v;
                const float* xbase = g_hT + (ks * 64) * 16;
                #pragma unroll 8
                for (int i = 0; i < 64; i++) {
                    const ulonglong2* xr = (const ulonglong2*)(xbase + i * 16);
                    ulonglong2 x0 = xr[0], x1 = xr[1], x2 = xr[2], x3 = xr[3];
                    float w = wptr[(size_t)i * 10000];
                    ull wb = pk(w, w);
                    acc[0] = f2(x0.x, wb, acc[0]); acc[1] = f2(x0.y, wb, acc[1]);
                    acc[2] = f2(x1.x, wb, acc[2]); acc[3] = f2(x1.y, wb, acc[3]);
                    acc[4] = f2(x2.x, wb, acc[4]); acc[5] = f2(x2.y, wb, acc[5]);
                    acc[6] = f2(x3.x, wb, acc[6]); acc[7] = f2(x3.y, wb, acc[7]);
                }
            }
            #pragma unroll
            for (int j = 0; j < 8; j++) {
                float2 vv = upk(acc[j]);
                s_red[ks][c][2 * j + 0] = vv.x;
                s_red[ks][c][2 * j + 1] = vv.y;
            }
            __syncthreads();
            #pragma unroll
            for (int r = 0; r < 2; r++) {
                int o = tid + r * 256;
                int c2 = o >> 4, b = o & 15;
                float s = 0.f;
                #pragma unroll
                for (int k = 0; k < 8; k++) s += s_red[k][c2][b];
                int vv = v0 + c2;
                if (vv < 10000) {
                    bool act = g_dlen[b] > tp;
                    out[OFF_PRED + (size_t)(b * 31 + tp) * 10000 + vv] =
                        act ? (s + fcB[vv]) : 0.f;
                }
            }
            __syncthreads();
        }
    };

    for (int t = 0; t < 31; t++) {
        if (bid < 64) {
            // ---------- A1: att2 + gate GEMV (2048 virtual cols, K=512) ---
            float (*s_red)[32][16] = (float(*)[32][16])sbuf;
            int c = tid & 31, ks = tid >> 5;
            int c0 = bid * 32;
            int col = c0 + c;
            const float* wptr = (col < 1024)
                ? (decW + (size_t)(ks * 64) * 1024 + col)
                : (fbW + (size_t)(ks * 64) * 1024 + (col - 1024));
            const float* xbase = g_xT + (1536 + ks * 64) * 16;
            ull acc[8];
            #pragma unroll
            for (int j = 0; j < 8; j++) acc[j] = 0ull;
            #pragma unroll 8
            for (int i = 0; i < 64; i++) {
                const ulonglong2* xr = (const ulonglong2*)(xbase + i * 16);
                ulonglong2 x0 = xr[0], x1 = xr[1], x2 = xr[2], x3 = xr[3];
                float w = wptr[(size_t)i * 1024];
                ull wb = pk(w, w);
                acc[0] = f2(x0.x, wb, acc[0]); acc[1] = f2(x0.y, wb, acc[1]);
                acc[2] = f2(x1.x, wb, acc[2]); acc[3] = f2(x1.y, wb, acc[3]);
                acc[4] = f2(x2.x, wb, acc[4]); acc[5] = f2(x2.y, wb, acc[5]);
                acc[6] = f2(x3.x, wb, acc[6]); acc[7] = f2(x3.y, wb, acc[7]);
            }
            #pragma unroll
            for (int j = 0; j < 8; j++) {
                float2 v = upk(acc[j]);
                s_red[ks][c][2 * j + 0] = v.x;
                s_red[ks][c][2 * j + 1] = v.y;
            }
            __syncthreads();
            #pragma unroll
            for (int r = 0; r < 2; r++) {
                int o = tid + r * 256;
                int c2 = o >> 4, b = o & 15;
                float s = 0.f;
                #pragma unroll
                for (int k = 0; k < 8; k++) s += s_red[k][c2][b];
                int ocol = c0 + c2;
                if (ocol < 1024) g_att2[b * 1024 + ocol] = s + decB[ocol];
                else g_gate[b * 1024 + (ocol - 1024)] = sigmf(s + fbB[ocol - 1024]);
            }
            // ---------- partial barrier over blocks 0..63 -----------------
            bar_sync(&g_cntA, &g_genA, 64, mygenA);

            if (bid < 16) {
                // ---------- A2: fused scores+softmax+alphas+awe (1 batch) -
                float* s_att2 = sbuf;            // 1024
                float* s_fw   = sbuf + 1024;     // 1024
                float* s_al   = sbuf + 2048;     // 200 (scores then alphas)
                float* s_rd   = sbuf + 2304;     // 8
                float* s_sc   = sbuf + 2336;     // 1
                int b = bid;
                for (int j = tid; j < 1024; j += 256) {
                    s_att2[j] = g_att2[b * 1024 + j];
                    s_fw[j]   = fullW[j];
                }
                __syncthreads();
                // scores: warp per row
                float fb0 = fullB[0];
                int wid = tid >> 5, lane = tid & 31;
                #pragma unroll 2
                for (int p = wid; p < 196; p += 8) {
                    const float* row = g_att1 + (size_t)(b * 196 + p) * 1024;
                    float acc = 0.f;
                    #pragma unroll
                    for (int eq = 0; eq < 8; eq++) {
                        int e = eq * 128 + lane * 4;
                        float4 x  = *(const float4*)(row + e);
                        float4 a2 = *(const float4*)&s_att2[e];
                        float4 w  = *(const float4*)&s_fw[e];
                        acc += fmaxf(x.x + a2.x, 0.f) * w.x;
                        acc += fmaxf(x.y + a2.y, 0.f) * w.y;
                        acc += fmaxf(x.z + a2.z, 0.f) * w.z;
                        acc += fmaxf(x.w + a2.w, 0.f) * w.w;
                    }
                    #pragma unroll
                    for (int o = 16; o > 0; o >>= 1)
                        acc += __shfl_xor_sync(0xffffffffu, acc, o);
                    if (lane == 0) s_al[p] = acc + fb0;
                }
                __syncthreads();
                // softmax over 196
                float sc = (tid < 196) ? s_al[tid] : -1e30f;
                float v = sc;
                #pragma unroll
                for (int o = 16; o > 0; o >>= 1)
                    v = fmaxf(v, __shfl_xor_sync(0xffffffffu, v, o));
                if (lane == 0) s_rd[wid] = v;
                __syncthreads();
                if (tid == 0) {
                    float m = s_rd[0];
                    #pragma unroll
                    for (int i = 1; i < 8; i++) m = fmaxf(m, s_rd[i]);
                    s_sc[0] = m;
                }
                __syncthreads();
                float ex = (tid < 196) ? expf(sc - s_sc[0]) : 0.f;
                v = ex;
                #pragma unroll
                for (int o = 16; o > 0; o >>= 1)
                    v += __shfl_xor_sync(0xffffffffu, v, o);
                if (lane == 0) s_rd[wid] = v;
                __syncthreads();
                if (tid == 0) {
                    float s = 0.f;
                    #pragma unroll
                    for (int i = 0; i < 8; i++) s += s_rd[i];
                    s_sc[0] = 1.0f / s;
                }
                __syncthreads();
                float alpha = ex * s_sc[0];
                bool act = g_dlen[b] > t;
                if (tid < 196) {
                    s_al[tid] = alpha;
                    out[OFF_ALPH + (size_t)(b * 31 + t) * 196 + tid] = act ? alpha : 0.f;
                }
                __syncthreads();
                // awe: 256 thr x 4 e
                int e4 = tid * 4;
                const float* ep = enc + ((size_t)g_sort[b] * 196) * 1024 + e4;
                float ax = 0.f, ay = 0.f, az = 0.f, aw = 0.f;
                #pragma unroll 16
                for (int p = 0; p < 196; p++) {
                    float al = s_al[p];
                    float4 ev = *(const float4*)(ep + (size_t)p * 1024);
                    ax += al * ev.x; ay += al * ev.y;
                    az += al * ev.z; aw += al * ev.w;
                }
                const float* gr = g_gate + b * 1024 + e4;
                g_xT[(512 + e4 + 0) * 16 + b] = ax + gr[0];
                g_xT[(512 + e4 + 1) * 16 + b] = ay + gr[1];
                g_xT[(512 + e4 + 2) * 16 + b] = az + gr[2];
                g_xT[(512 + e4 + 3) * 16 + b] = aw + gr[3];
            } else {
                // ---------- emb fill on blocks 16..63 ---------------------
                int j = (bid - 16) * 256 + tid;
                if (j < 8192) {
                    int b = j >> 9, k = j & 511;
                    int tok = g_caps[b * 32 + t];
                    g_xT[k * 16 + b] = emb[(size_t)tok * 512 + k];
                }
            }
        } else {
            // ---------- group B: vocab projection for t-1 -----------------
            if (t > 0) phaseE(t - 1, bid - 64, 84);
        }
        bar_sync(&g_cnt, &g_gen, NBLK, mygen);

        // ============ fused LSTM gates GEMM + elementwise =================
        if (bid < 128) {
            float (*s_red)[16][16] = (float(*)[16][16])sbuf;     // 4096
            float (*s_gt)[16] = (float(*)[16])(sbuf + 4096);     // 256
            int d0 = bid * 4;
            int c = tid & 15, ks = tid >> 4;
            int gg = c >> 2, dd = c & 3;
            int col = gg * 512 + d0 + dd;
            const float* wptr = (ks < 12)
                ? (Wih + (size_t)(ks * 128) * 2048 + col)
                : (Whh + (size_t)((ks - 12) * 128) * 2048 + col);
            const float* xbase = g_xT + (ks * 128) * 16;
            ull acc[8];
            #pragma unroll
            for (int j = 0; j < 8; j++) acc[j] = 0ull;
            #pragma unroll 8
            for (int i = 0; i < 128; i++) {
                const ulonglong2* xr = (const ulonglong2*)(xbase + i * 16);
                ulonglong2 x0 = xr[0], x1 = xr[1], x2 = xr[2], x3 = xr[3];
                float w = wptr[(size_t)i * 2048];
                ull wb = pk(w, w);
                acc[0] = f2(x0.x, wb, acc[0]); acc[1] = f2(x0.y, wb, acc[1]);
                acc[2] = f2(x1.x, wb, acc[2]); acc[3] = f2(x1.y, wb, acc[3]);
                acc[4] = f2(x2.x, wb, acc[4]); acc[5] = f2(x2.y, wb, acc[5]);
                acc[6] = f2(x3.x, wb, acc[6]); acc[7] = f2(x3.y, wb, acc[7]);
            }
            #pragma unroll
            for (int j = 0; j < 8; j++) {
                float2 v = upk(acc[j]);
                s_red[ks][c][2 * j + 0] = v.x;
                s_red[ks][c][2 * j + 1] = v.y;
            }
            __syncthreads();
            {   // one (c,b) per thread
                int c2 = tid >> 4, b = tid & 15;
                float s = 0.f;
                #pragma unroll
                for (int k = 0; k < 16; k++) s += s_red[k][c2][b];
                int col2 = (c2 >> 2) * 512 + d0 + (c2 & 3);
                s_gt[c2][b] = s + bih[col2] + bhh[col2];
            }
            __syncthreads();
            if (tid < 64) {
                int dd2 = tid >> 4, b = tid & 15;
                int d = d0 + dd2;
                float gi = s_gt[0 + dd2][b];
                float gf = s_gt[4 + dd2][b];
                float gc = s_gt[8 + dd2][b];
                float go = s_gt[12 + dd2][b];
                int gid = b * 512 + d;
                float cold = g_c[gid];
                float cnew = sigmf(gf) * cold + sigmf(gi) * tanhf(gc);
                float hnew = sigmf(go) * tanhf(cnew);
                bool act = g_dlen[b] > t;
                float h2 = act ? hnew : g_h[gid];
                float c2v = act ? cnew : cold;
                g_h[gid] = h2;
                g_c[gid] = c2v;
                g_hT[d * 16 + b] = hnew;
                g_xT[(1536 + d) * 16 + b] = h2;
            }
        }
        bar_sync(&g_cnt, &g_gen, NBLK, mygen);
    }

    // final vocab projection for t = 30 on all 148 blocks
    phaseE(30, bid, NBLK);
}

// ================= launcher ==============================================
extern "C" void kernel_launch(void* const* d_in, const int* in_sizes, int n_in,
                              void* d_out, int out_size) {
    const float* enc    = (const float*)d_in[0];
    const float* encW   = (const float*)d_in[1];
    const float* encB   = (const float*)d_in[2];
    const float* decW   = (const float*)d_in[3];
    const float* decB   = (const float*)d_in[4];
    const float* fullW  = (const float*)d_in[5];
    const float* fullB  = (const float*)d_in[6];
    const float* emb    = (const float*)d_in[7];
    const float* Wih    = (const float*)d_in[8];
    const float* bih    = (const float*)d_in[9];
    const float* Whh    = (const float*)d_in[10];
    const float* bhh    = (const float*)d_in[11];
    const float* ihW    = (const float*)d_in[12];
    const float* ihB    = (const float*)d_in[13];
    const float* icW    = (const float*)d_in[14];
    const float* icB    = (const float*)d_in[15];
    const float* fbW    = (const float*)d_in[16];
    const float* fbB    = (const float*)d_in[17];
    const float* fcW    = (const float*)d_in[18];
    const float* fcB    = (const float*)d_in[19];
    const int*   capsin = (const int*)d_in[20];
    const int*   clen   = (const int*)d_in[21];
    float* out = (float*)d_out;

    ksetup1<<<1, 256>>>(capsin, clen, out);
    ksetup2<<<64, 256>>>(enc);
    ksetup3<<<64, 256>>>(ihW, ihB, icW, icB);
    katt1<<<dim3(8, 25), 256>>>(enc, encW, encB);
    kstep<<<NBLK, 256>>>(enc, decW, decB, fullW, fullB, fbW, fbB, emb,
                         Wih, bih, Whh, bhh, fcW, fcB, out);
}

// round 5
// speedup vs baseline: 1.8764x; 1.0807x over previous
#include <cuda_runtime.h>
#include <cstdint>
#include <cstddef>

typedef unsigned long long ull;

// ---------------- output layout (float32 concat of reference tuple) -------
#define OFF_PRED 0
#define OFF_CAPS 4960000
#define OFF_DLEN 4960512
#define OFF_ALPH 4960528
#define OFF_SORT 5057744

#define NBLK 148

// ---------------- device scratch (static globals: no allocs) --------------
__device__ int   g_sort[16], g_dlen[16], g_caps[512];
__device__ float g_mean[16 * 1024];
__device__ float g_att1[3136 * 1024];     // 12.8 MB
__device__ float g_h[16 * 512], g_c[16 * 512];
__device__ float g_hT[512 * 16];          // h_new transposed [d][b]
__device__ float g_xT[2048 * 16];         // X transposed [k][b]: emb|awe|h
__device__ float g_att2[16 * 1024], g_gate[16 * 1024];
__device__ unsigned g_cnt = 0, g_gen = 0;       // full barrier
__device__ unsigned g_cntA = 0, g_genA = 0;     // partial (64-block) barrier

// ---------------- helpers ----------------
__device__ __forceinline__ ull pk(float x, float y) {
    ull u; asm("mov.b64 %0,{%1,%2};" : "=l"(u) : "f"(x), "f"(y)); return u;
}
__device__ __forceinline__ float2 upk(ull u) {
    float2 v; asm("mov.b64 {%0,%1},%2;" : "=f"(v.x), "=f"(v.y) : "l"(u)); return v;
}
__device__ __forceinline__ ull f2(ull a, ull b, ull c) {
    ull d; asm("fma.rn.f32x2 %0,%1,%2,%3;" : "=l"(d) : "l"(a), "l"(b), "l"(c)); return d;
}
__device__ __forceinline__ ull addf2(ull a, ull b) {
    ull d; asm("add.rn.f32x2 %0,%1,%2;" : "=l"(d) : "l"(a), "l"(b)); return d;
}
__device__ __forceinline__ float sigmf(float x) { return 1.f / (1.f + expf(-x)); }

__device__ __forceinline__ void bar_sync(unsigned* cnt, unsigned* gen,
                                         unsigned count, unsigned& mygen) {
    __syncthreads();
    if (threadIdx.x == 0) {
        __threadfence();
        if (atomicAdd(cnt, 1u) == count - 1) {
            *cnt = 0;
            __threadfence();
            *(volatile unsigned*)gen = mygen + 1;
        } else {
            while (*(volatile unsigned*)gen == mygen) { }
            __threadfence();
        }
    }
    mygen++;
    __syncthreads();
}

// ================= setup 1: stable sort + caps/dlen/sort_ind out ==========
__global__ void ksetup1(const int* __restrict__ caps_in,
                        const int* __restrict__ clen,
                        float* __restrict__ out) {
    int tid = threadIdx.x;
    if (tid == 0) {
        int len[16];
        #pragma unroll
        for (int i = 0; i < 16; i++) len[i] = clen[i];
        for (int i = 0; i < 16; i++) {
            int rank = 0;
            for (int j = 0; j < 16; j++)
                rank += (len[j] > len[i]) || (len[j] == len[i] && j < i);
            g_sort[rank] = i;
            g_dlen[rank] = len[i] - 1;
            out[OFF_SORT + rank] = (float)i;
            out[OFF_DLEN + rank] = (float)(len[i] - 1);
        }
    }
    __syncthreads();
    for (int j = tid; j < 512; j += 256) {
        int b = j >> 5, l = j & 31;
        int v = caps_in[g_sort[b] * 32 + l];
        g_caps[j] = v;
        out[OFF_CAPS + j] = (float)v;
    }
}

// ================= setup 2: mean over P of sorted encoder ==================
__global__ void ksetup2(const float* __restrict__ enc) {
    int j = blockIdx.x * 256 + threadIdx.x;   // 16384 = 16 b x 1024 e
    int b = j >> 10, e = j & 1023;
    const float* p0 = enc + ((size_t)g_sort[b] * 196) * 1024 + e;
    float s = 0.f;
    #pragma unroll 8
    for (int p = 0; p < 196; p++) s += p0[(size_t)p * 1024];
    g_mean[j] = s * (1.0f / 196.0f);
}

// ================= setup 3: h0, c0 (also fill xT h-rows) ===================
__global__ void ksetup3(const float* __restrict__ ihW, const float* __restrict__ ihB,
                        const float* __restrict__ icW, const float* __restrict__ icB) {
    int j = blockIdx.x * 256 + threadIdx.x;   // 16384 = 2 x 16 b x 512 d
    int which = j >> 13;
    int jj = j & 8191;
    int b = jj >> 9, d = jj & 511;
    const float* W = which ? icW : ihW;
    const float* mrow = g_mean + b * 1024;
    float acc = 0.f;
    #pragma unroll 8
    for (int k = 0; k < 1024; k++) acc += mrow[k] * W[k * 512 + d];
    float val = acc + (which ? icB[d] : ihB[d]);
    if (which) g_c[b * 512 + d] = val;
    else { g_h[b * 512 + d] = val; g_xT[(1536 + d) * 16 + b] = val; }
}

// ================= att1 GEMM (unchanged) ===================================
__global__ void __launch_bounds__(256, 1)
katt1(const float* __restrict__ enc, const float* __restrict__ W,
      const float* __restrict__ bias) {
    __shared__ float As[32][132];
    __shared__ float Bs[32][128];
    int tid = threadIdx.x;
    int bm = blockIdx.y, bn = blockIdx.x;

    int kq = tid & 7, ml = tid >> 3;
    const float* arow[4];
    #pragma unroll
    for (int ps = 0; ps < 4; ps++) {
        int m = bm * 128 + ml + ps * 32;
        int mc = m < 3135 ? m : 3135;
        int b = mc / 196, p = mc - b * 196;
        arow[ps] = enc + ((size_t)g_sort[b] * 196 + p) * 1024 + kq * 4;
    }
    int nb = tid & 31, kb = tid >> 5;
    const float* bptr = W + (size_t)kb * 1024 + bn * 128 + nb * 4;

    ull acc[8][4];
    #pragma unroll
    for (int i = 0; i < 8; i++)
        #pragma unroll
        for (int j = 0; j < 4; j++) acc[i][j] = 0ull;

    int tx = tid & 15, ty = tid >> 4;

    float4 ra[4], rb[4];
    #pragma unroll
    for (int ps = 0; ps < 4; ps++) ra[ps] = *(const float4*)(arow[ps]);
    #pragma unroll
    for (int ps = 0; ps < 4; ps++) rb[ps] = *(const float4*)(bptr + (size_t)(ps * 8) * 1024);

    for (int kt = 0; kt < 1024; kt += 32) {
        #pragma unroll
        for (int ps = 0; ps < 4; ps++) {
            int mm = ml + ps * 32;
            As[kq * 4 + 0][mm] = ra[ps].x;
            As[kq * 4 + 1][mm] = ra[ps].y;
            As[kq * 4 + 2][mm] = ra[ps].z;
            As[kq * 4 + 3][mm] = ra[ps].w;
        }
        #pragma unroll
        for (int ps = 0; ps < 4; ps++)
            *(float4*)&Bs[kb + ps * 8][nb * 4] = rb[ps];
        __syncthreads();
        if (kt + 32 < 1024) {
            #pragma unroll
            for (int ps = 0; ps < 4; ps++)
                ra[ps] = *(const float4*)(arow[ps] + kt + 32);
            #pragma unroll
            for (int ps = 0; ps < 4; ps++)
                rb[ps] = *(const float4*)(bptr + (size_t)(kt + 32 + ps * 8) * 1024);
        }
        #pragma unroll 8
        for (int kk = 0; kk < 32; kk++) {
            float4 a0 = *(const float4*)&As[kk][ty * 8];
            float4 a1 = *(const float4*)&As[kk][ty * 8 + 4];
            ulonglong2 b0 = *(const ulonglong2*)&Bs[kk][tx * 8];
            ulonglong2 b1 = *(const ulonglong2*)&Bs[kk][tx * 8 + 4];
            float a[8] = {a0.x, a0.y, a0.z, a0.w, a1.x, a1.y, a1.z, a1.w};
            #pragma unroll
            for (int i = 0; i < 8; i++) {
                ull ap = pk(a[i], a[i]);
                acc[i][0] = f2(ap, b0.x, acc[i][0]);
                acc[i][1] = f2(ap, b0.y, acc[i][1]);
                acc[i][2] = f2(ap, b1.x, acc[i][2]);
                acc[i][3] = f2(ap, b1.y, acc[i][3]);
            }
        }
        __syncthreads();
    }
    int n0 = bn * 128 + tx * 8;
    float bb[8];
    #pragma unroll
    for (int j = 0; j < 8; j++) bb[j] = bias[n0 + j];
    #pragma unroll
    for (int i = 0; i < 8; i++) {
        int m = bm * 128 + ty * 8 + i;
        if (m < 3136) {
            float* dst = g_att1 + (size_t)m * 1024 + n0;
            #pragma unroll
            for (int j = 0; j < 4; j++) {
                float2 v = upk(acc[i][j]);
                dst[2 * j + 0] = v.x + bb[2 * j + 0];
                dst[2 * j + 1] = v.y + bb[2 * j + 1];
            }
        }
    }
}

// ================= persistent step kernel ==================================
__global__ void __launch_bounds__(256, 1)
kstep(const float* __restrict__ enc,
      const float* __restrict__ decW, const float* __restrict__ decB,
      const float* __restrict__ fullW, const float* __restrict__ fullB,
      const float* __restrict__ fbW, const float* __restrict__ fbB,
      const float* __restrict__ emb,
      const float* __restrict__ Wih, const float* __restrict__ bih,
      const float* __restrict__ Whh, const float* __restrict__ bhh,
      const float* __restrict__ fcW, const float* __restrict__ fcB,
      float* __restrict__ out)
{
    __shared__ ull sb8[4096];           // 32KB, reused per phase
    float* sbuf = (float*)sb8;
    const int tid = threadIdx.x;
    const int bid = blockIdx.x;
    const int lane = tid & 31;
    const int wrp  = tid >> 5;
    unsigned mygen  = *(volatile unsigned*)&g_gen;
    unsigned mygenA = *(volatile unsigned*)&g_genA;

    // -------- phase E: vocab projection for step tp (reads g_hT) ----------
    // chunk = 128 vocab cols; 79 chunks total. 4 cols/thread via float4 w.
    // lane = col-group (32), warp = k-slice (8 x 64).
    auto phaseE = [&](int tp, int start, int stride) {
        // sb8 viewed as [4][32][4][8]
        for (int ch = start; ch < 79; ch += stride) {
            int v0 = ch * 128;
            int vcol = v0 + lane * 4;
            ull acc[4][8];
            #pragma unroll
            for (int c = 0; c < 4; c++)
                #pragma unroll
                for (int j = 0; j < 8; j++) acc[c][j] = 0ull;
            if (vcol < 10000) {
                const float* wp = fcW + (size_t)(wrp * 64) * 10000 + vcol;
                const float* xb = g_hT + (wrp * 64) * 16;
                #pragma unroll 4
                for (int i = 0; i < 64; i++) {
                    float4 w4 = *(const float4*)(wp + (size_t)i * 10000);
                    const ulonglong2* xr = (const ulonglong2*)(xb + i * 16);
                    ulonglong2 x0 = xr[0], x1 = xr[1], x2 = xr[2], x3 = xr[3];
                    ull xv[8] = {x0.x, x0.y, x1.x, x1.y, x2.x, x2.y, x3.x, x3.y};
                    float wf[4] = {w4.x, w4.y, w4.z, w4.w};
                    #pragma unroll
                    for (int c = 0; c < 4; c++) {
                        ull wb = pk(wf[c], wf[c]);
                        #pragma unroll
                        for (int j = 0; j < 8; j++)
                            acc[c][j] = f2(xv[j], wb, acc[c][j]);
                    }
                }
            }
            // two-pass smem reduction over 8 warps -> 4 pair-partials
            ull* s = sb8;   // [p][lane][c][j] : ((p*32+lane)*4+c)*8+j
            if (wrp < 4) {
                #pragma unroll
                for (int c = 0; c < 4; c++)
                    #pragma unroll
                    for (int j = 0; j < 8; j++)
                        s[(((wrp) * 32 + lane) * 4 + c) * 8 + j] = acc[c][j];
            }
            __syncthreads();
            if (wrp >= 4) {
                int p = wrp - 4;
                #pragma unroll
                for (int c = 0; c < 4; c++)
                    #pragma unroll
                    for (int j = 0; j < 8; j++) {
                        int idx = (((p) * 32 + lane) * 4 + c) * 8 + j;
                        s[idx] = addf2(s[idx], acc[c][j]);
                    }
            }
            __syncthreads();
            // final: 1024 ull outputs: col = o&127, bp = o>>7
            #pragma unroll
            for (int q = 0; q < 4; q++) {
                int o = q * 256 + tid;
                int col = o & 127, bp = o >> 7;
                int v = v0 + col;
                if (v < 10000) {
                    int cg = col >> 2, cc = col & 3;
                    ull sm = s[((0 * 32 + cg) * 4 + cc) * 8 + bp];
                    sm = addf2(sm, s[((1 * 32 + cg) * 4 + cc) * 8 + bp]);
                    sm = addf2(sm, s[((2 * 32 + cg) * 4 + cc) * 8 + bp]);
                    sm = addf2(sm, s[((3 * 32 + cg) * 4 + cc) * 8 + bp]);
                    float2 r = upk(sm);
                    float fb = fcB[v];
                    int b0 = 2 * bp, b1 = b0 + 1;
                    out[OFF_PRED + (size_t)(b0 * 31 + tp) * 10000 + v] =
                        (g_dlen[b0] > tp) ? (r.x + fb) : 0.f;
                    out[OFF_PRED + (size_t)(b1 * 31 + tp) * 10000 + v] =
                        (g_dlen[b1] > tp) ? (r.y + fb) : 0.f;
                }
            }
            __syncthreads();
        }
    };

    for (int t = 0; t < 31; t++) {
        if (bid < 64) {
            // ---------- A1: att2 + gate GEMV (2048 virt cols, K=512) ------
            // 32 cols/block: cg = tid&7 (4 cols via float4), ks = tid>>3 (32)
            {
                int cg = tid & 7, ks = tid >> 3;
                int c0 = bid * 32;
                int colg = c0 + cg * 4;
                const float* wp = (colg < 1024)
                    ? (decW + (size_t)(ks * 16) * 1024 + colg)
                    : (fbW + (size_t)(ks * 16) * 1024 + (colg - 1024));
                const float* xb = g_xT + (1536 + ks * 16) * 16;
                ull acc[4][8];
                #pragma unroll
                for (int c = 0; c < 4; c++)
                    #pragma unroll
                    for (int j = 0; j < 8; j++) acc[c][j] = 0ull;
                #pragma unroll 4
                for (int i = 0; i < 16; i++) {
                    float4 w4 = *(const float4*)(wp + (size_t)i * 1024);
                    const ulonglong2* xr = (const ulonglong2*)(xb + i * 16);
                    ulonglong2 x0 = xr[0], x1 = xr[1], x2 = xr[2], x3 = xr[3];
                    ull xv[8] = {x0.x, x0.y, x1.x, x1.y, x2.x, x2.y, x3.x, x3.y};
                    float wf[4] = {w4.x, w4.y, w4.z, w4.w};
                    #pragma unroll
                    for (int c = 0; c < 4; c++) {
                        ull wb = pk(wf[c], wf[c]);
                        #pragma unroll
                        for (int j = 0; j < 8; j++)
                            acc[c][j] = f2(xv[j], wb, acc[c][j]);
                    }
                }
                // warp shfl reduce over k-slices (xor 8, 16)
                #pragma unroll
                for (int c = 0; c < 4; c++)
                    #pragma unroll
                    for (int j = 0; j < 8; j++) {
                        acc[c][j] = addf2(acc[c][j],
                            __shfl_xor_sync(0xffffffffu, acc[c][j], 8));
                        acc[c][j] = addf2(acc[c][j],
                            __shfl_xor_sync(0xffffffffu, acc[c][j], 16));
                    }
                // lanes 0..7 store: s[w][cg][c][j] : [8][8][4][8]
                if (lane < 8) {
                    #pragma unroll
                    for (int c = 0; c < 4; c++)
                        #pragma unroll
                        for (int j = 0; j < 8; j++)
                            sb8[(((wrp) * 8 + lane) * 4 + c) * 8 + j] = acc[c][j];
                }
                __syncthreads();
                // final: o = tid: col = o>>3 (32), bp = o&7
                {
                    int col = tid >> 3, bp = tid & 7;
                    int cg2 = col >> 2, cc = col & 3;
                    ull sm = sb8[((0 * 8 + cg2) * 4 + cc) * 8 + bp];
                    #pragma unroll
                    for (int w = 1; w < 8; w++)
                        sm = addf2(sm, sb8[((w * 8 + cg2) * 4 + cc) * 8 + bp]);
                    float2 r = upk(sm);
                    int ocol = c0 + col;
                    int b0 = 2 * bp, b1 = b0 + 1;
                    if (ocol < 1024) {
                        float db = decB[ocol];
                        g_att2[b0 * 1024 + ocol] = r.x + db;
                        g_att2[b1 * 1024 + ocol] = r.y + db;
                    } else {
                        int oc = ocol - 1024;
                        float fb = fbB[oc];
                        g_gate[b0 * 1024 + oc] = sigmf(r.x + fb);
                        g_gate[b1 * 1024 + oc] = sigmf(r.y + fb);
                    }
                }
            }
            // ---------- partial barrier over blocks 0..63 -----------------
            bar_sync(&g_cntA, &g_genA, 64, mygenA);

            if (bid < 16) {
                // ---------- A2: fused scores+softmax+alphas+awe (1 batch) -
                float* s_att2 = sbuf;            // 1024
                float* s_fw   = sbuf + 1024;     // 1024
                float* s_al   = sbuf + 2048;     // 200
                float* s_rd   = sbuf + 2304;     // 8
                float* s_sc   = sbuf + 2336;     // 1
                int b = bid;
                for (int j = tid; j < 1024; j += 256) {
                    s_att2[j] = g_att2[b * 1024 + j];
                    s_fw[j]   = fullW[j];
                }
                __syncthreads();
                float fb0 = fullB[0];
                #pragma unroll 2
                for (int p = wrp; p < 196; p += 8) {
                    const float* row = g_att1 + (size_t)(b * 196 + p) * 1024;
                    float acc = 0.f;
                    #pragma unroll
                    for (int eq = 0; eq < 8; eq++) {
                        int e = eq * 128 + lane * 4;
                        float4 x  = *(const float4*)(row + e);
                        float4 a2 = *(const float4*)&s_att2[e];
                        float4 w  = *(const float4*)&s_fw[e];
                        acc += fmaxf(x.x + a2.x, 0.f) * w.x;
                        acc += fmaxf(x.y + a2.y, 0.f) * w.y;
                        acc += fmaxf(x.z + a2.z, 0.f) * w.z;
                        acc += fmaxf(x.w + a2.w, 0.f) * w.w;
                    }
                    #pragma unroll
                    for (int o = 16; o > 0; o >>= 1)
                        acc += __shfl_xor_sync(0xffffffffu, acc, o);
                    if (lane == 0) s_al[p] = acc + fb0;
                }
                __syncthreads();
                float sc = (tid < 196) ? s_al[tid] : -1e30f;
                float v = sc;
                #pragma unroll
                for (int o = 16; o > 0; o >>= 1)
                    v = fmaxf(v, __shfl_xor_sync(0xffffffffu, v, o));
                if (lane == 0) s_rd[wrp] = v;
                __syncthreads();
                if (tid == 0) {
                    float m = s_rd[0];
                    #pragma unroll
                    for (int i = 1; i < 8; i++) m = fmaxf(m, s_rd[i]);
                    s_sc[0] = m;
                }
                __syncthreads();
                float ex = (tid < 196) ? expf(sc - s_sc[0]) : 0.f;
                v = ex;
                #pragma unroll
                for (int o = 16; o > 0; o >>= 1)
                    v += __shfl_xor_sync(0xffffffffu, v, o);
                if (lane == 0) s_rd[wrp] = v;
                __syncthreads();
                if (tid == 0) {
                    float s = 0.f;
                    #pragma unroll
                    for (int i = 0; i < 8; i++) s += s_rd[i];
                    s_sc[0] = 1.0f / s;
                }
                __syncthreads();
                float alpha = ex * s_sc[0];
                bool act = g_dlen[b] > t;
                if (tid < 196) {
                    s_al[tid] = alpha;
                    out[OFF_ALPH + (size_t)(b * 31 + t) * 196 + tid] = act ? alpha : 0.f;
                }
                __syncthreads();
                int e4 = tid * 4;
                const float* ep = enc + ((size_t)g_sort[b] * 196) * 1024 + e4;
                float ax = 0.f, ay = 0.f, az = 0.f, aw = 0.f;
                #pragma unroll 16
                for (int p = 0; p < 196; p++) {
                    float al = s_al[p];
                    float4 ev = *(const float4*)(ep + (size_t)p * 1024);
                    ax += al * ev.x; ay += al * ev.y;
                    az += al * ev.z; aw += al * ev.w;
                }
                const float* gr = g_gate + b * 1024 + e4;
                g_xT[(512 + e4 + 0) * 16 + b] = ax + gr[0];
                g_xT[(512 + e4 + 1) * 16 + b] = ay + gr[1];
                g_xT[(512 + e4 + 2) * 16 + b] = az + gr[2];
                g_xT[(512 + e4 + 3) * 16 + b] = aw + gr[3];
            } else {
                // ---------- emb fill on blocks 16..63 ---------------------
                int j = (bid - 16) * 256 + tid;
                if (j < 8192) {
                    int b = j >> 9, k = j & 511;
                    int tok = g_caps[b * 32 + t];
                    g_xT[k * 16 + b] = emb[(size_t)tok * 512 + k];
                }
            }
        } else {
            // ---------- group B: vocab projection for t-1 -----------------
            if (t > 0) phaseE(t - 1, bid - 64, 84);
        }
        bar_sync(&g_cnt, &g_gen, NBLK, mygen);

        // ============ fused LSTM gates GEMM + elementwise =================
        if (bid < 128) {
            // 16 cols/block (4 gates x 4 d). cg = tid&3 -> gate, ks = tid>>2
            int d0 = bid * 4;
            int cg = tid & 3, ks = tid >> 2;
            int col = cg * 512 + d0;
            const float* wp = (ks < 48)
                ? (Wih + (size_t)(ks * 32) * 2048 + col)
                : (Whh + (size_t)((ks - 48) * 32) * 2048 + col);
            const float* xb = g_xT + (ks * 32) * 16;
            ull acc[4][8];
            #pragma unroll
            for (int c = 0; c < 4; c++)
                #pragma unroll
                for (int j = 0; j < 8; j++) acc[c][j] = 0ull;
            #pragma unroll 4
            for (int i = 0; i < 32; i++) {
                float4 w4 = *(const float4*)(wp + (size_t)i * 2048);
                const ulonglong2* xr = (const ulonglong2*)(xb + i * 16);
                ulonglong2 x0 = xr[0], x1 = xr[1], x2 = xr[2], x3 = xr[3];
                ull xv[8] = {x0.x, x0.y, x1.x, x1.y, x2.x, x2.y, x3.x, x3.y};
                float wf[4] = {w4.x, w4.y, w4.z, w4.w};
                #pragma unroll
                for (int c = 0; c < 4; c++) {
                    ull wb = pk(wf[c], wf[c]);
                    #pragma unroll
                    for (int j = 0; j < 8; j++)
                        acc[c][j] = f2(xv[j], wb, acc[c][j]);
                }
            }
            // warp shfl reduce over ks (xor 4, 8, 16)
            #pragma unroll
            for (int c = 0; c < 4; c++)
                #pragma unroll
                for (int j = 0; j < 8; j++) {
                    acc[c][j] = addf2(acc[c][j],
                        __shfl_xor_sync(0xffffffffu, acc[c][j], 4));
                    acc[c][j] = addf2(acc[c][j],
                        __shfl_xor_sync(0xffffffffu, acc[c][j], 8));
                    acc[c][j] = addf2(acc[c][j],
                        __shfl_xor_sync(0xffffffffu, acc[c][j], 16));
                }
            // lanes 0..3 store: s[w][cg][c][j] : [8][4][4][8] = 1024 ull
            if (lane < 4) {
                #pragma unroll
                for (int c = 0; c < 4; c++)
                    #pragma unroll
                    for (int j = 0; j < 8; j++)
                        sb8[(((wrp) * 4 + lane) * 4 + c) * 8 + j] = acc[c][j];
            }
            float* s_gt = (float*)(sb8 + 1024);   // [16][16]
            __syncthreads();
            if (tid < 128) {
                int c = tid >> 3, bp = tid & 7;      // c: g*4+dd
                int g = c >> 2, dd = c & 3;
                ull sm = sb8[((0 * 4 + g) * 4 + dd) * 8 + bp];
                #pragma unroll
                for (int w = 1; w < 8; w++)
                    sm = addf2(sm, sb8[((w * 4 + g) * 4 + dd) * 8 + bp]);
                float2 r = upk(sm);
                int col2 = g * 512 + d0 + dd;
                float bb = bih[col2] + bhh[col2];
                s_gt[c * 16 + 2 * bp + 0] = r.x + bb;
                s_gt[c * 16 + 2 * bp + 1] = r.y + bb;
            }
            __syncthreads();
            if (tid < 64) {
                int dd2 = tid >> 4, b = tid & 15;
                int d = d0 + dd2;
                float gi = s_gt[(0 + dd2) * 16 + b];
                float gf = s_gt[(4 + dd2) * 16 + b];
                float gc = s_gt[(8 + dd2) * 16 + b];
                float go = s_gt[(12 + dd2) * 16 + b];
                int gid = b * 512 + d;
                float cold = g_c[gid];
                float cnew = sigmf(gf) * cold + sigmf(gi) * tanhf(gc);
                float hnew = sigmf(go) * tanhf(cnew);
                bool act = g_dlen[b] > t;
                float h2 = act ? hnew : g_h[gid];
                float c2v = act ? cnew : cold;
                g_h[gid] = h2;
                g_c[gid] = c2v;
                g_hT[d * 16 + b] = hnew;
                g_xT[(1536 + d) * 16 + b] = h2;
            }
        }
        bar_sync(&g_cnt, &g_gen, NBLK, mygen);
    }

    // final vocab projection for t = 30 on all blocks
    phaseE(30, bid, NBLK);
}

// ================= launcher ==============================================
extern "C" void kernel_launch(void* const* d_in, const int* in_sizes, int n_in,
                              void* d_out, int out_size) {
    const float* enc    = (const float*)d_in[0];
    const float* encW   = (const float*)d_in[1];
    const float* encB   = (const float*)d_in[2];
    const float* decW   = (const float*)d_in[3];
    const float* decB   = (const float*)d_in[4];
    const float* fullW  = (const float*)d_in[5];
    const float* fullB  = (const float*)d_in[6];
    const float* emb    = (const float*)d_in[7];
    const float* Wih    = (const float*)d_in[8];
    const float* bih    = (const float*)d_in[9];
    const float* Whh    = (const float*)d_in[10];
    const float* bhh    = (const float*)d_in[11];
    const float* ihW    = (const float*)d_in[12];
    const float* ihB    = (const float*)d_in[13];
    const float* icW    = (const float*)d_in[14];
    const float* icB    = (const float*)d_in[15];
    const float* fbW    = (const float*)d_in[16];
    const float* fbB    = (const float*)d_in[17];
    const float* fcW    = (const float*)d_in[18];
    const float* fcB    = (const float*)d_in[19];
    const int*   capsin = (const int*)d_in[20];
    const int*   clen   = (const int*)d_in[21];
    float* out = (float*)d_out;

    ksetup1<<<1, 256>>>(capsin, clen, out);
    ksetup2<<<64, 256>>>(enc);
    ksetup3<<<64, 256>>>(ihW, ihB, icW, icB);
    katt1<<<dim3(8, 25), 256>>>(enc, encW, encB);
    kstep<<<NBLK, 256>>>(enc, decW, decB, fullW, fullB, fbW, fbB, emb,
                         Wih, bih, Whh, bhh, fcW, fcB, out);
}